// round 1
// baseline (speedup 1.0000x reference)
#include <cuda_runtime.h>
#include <math.h>

#define BATCH 16
#define DIM   512
#define S     128
#define PLANE (S*S)            // 16384 floats per channel plane
#define PLANE4 (PLANE/4)       // 4096 float4

// Scratch (allocation-free rule: __device__ globals)
__device__ float g_x2[BATCH * 2 * PLANE];     // [b][o][h][w]  (2 MB)
__device__ float g_ww_raw[BATCH * S];
__device__ float g_hw_raw[BATCH * S];

// ---------------------------------------------------------------------------
// K1: 1x1 conv, 512 -> 2 channels. One thread per float4 pixel group.
// x: [B,512,S,S], wconv: [2,512]
// ---------------------------------------------------------------------------
__global__ void __launch_bounds__(128) k_conv1x1(const float* __restrict__ x,
                                                 const float* __restrict__ wconv) {
    __shared__ float2 s_wc[DIM];
    for (int c = threadIdx.x; c < DIM; c += blockDim.x)
        s_wc[c] = make_float2(wconv[c], wconv[DIM + c]);
    __syncthreads();

    int gid = blockIdx.x * blockDim.x + threadIdx.x;   // 0 .. 65535
    int b = gid >> 12;          // 4096 float4 groups per image plane
    int p = gid & 4095;

    const float4* xb = reinterpret_cast<const float4*>(x) + (size_t)b * DIM * PLANE4 + p;

    float4 a0 = make_float4(0.f, 0.f, 0.f, 0.f);
    float4 a1 = make_float4(0.f, 0.f, 0.f, 0.f);

#pragma unroll 8
    for (int c = 0; c < DIM; c++) {
        float4 v = xb[(size_t)c * PLANE4];
        float2 wc = s_wc[c];
        a0.x = fmaf(v.x, wc.x, a0.x); a0.y = fmaf(v.y, wc.x, a0.y);
        a0.z = fmaf(v.z, wc.x, a0.z); a0.w = fmaf(v.w, wc.x, a0.w);
        a1.x = fmaf(v.x, wc.y, a1.x); a1.y = fmaf(v.y, wc.y, a1.y);
        a1.z = fmaf(v.z, wc.y, a1.z); a1.w = fmaf(v.w, wc.y, a1.w);
    }

    float4* o = reinterpret_cast<float4*>(g_x2) + (size_t)b * 2 * PLANE4 + p;
    o[0]      = a0;
    o[PLANE4] = a1;
}

// ---------------------------------------------------------------------------
// K2: the two "strip conv" reductions. One warp per output scalar.
//   ww[b,w] = sum_{i,h,kw} x2[b,i,h,w+kw-2] * w_ww[i,h,kw]     (w_ww: [2,128,5])
//   hw[b,h] = sum_{i,kh,w} x2[b,i,h+kh-2,w] * w_hw[i,kh,w]     (w_hw: [2,5,128])
// 4096 warps total; x2 is L2-resident.
// ---------------------------------------------------------------------------
__global__ void __launch_bounds__(256) k_stripconv(const float* __restrict__ w_ww,
                                                   const float* __restrict__ w_hw) {
    int gwarp = (blockIdx.x * blockDim.x + threadIdx.x) >> 5;
    int lane  = threadIdx.x & 31;
    int branch = gwarp >> 11;          // 0 = ww, 1 = hw
    int idx    = gwarp & 2047;
    int b      = idx >> 7;
    int o      = idx & 127;            // w (ww branch) or h (hw branch)

    const float* x2b = g_x2 + (size_t)b * 2 * PLANE;
    float acc = 0.f;

    if (branch == 0) {
#pragma unroll
        for (int i = 0; i < 2; i++) {
#pragma unroll
            for (int kw = 0; kw < 5; kw++) {
                int w = o + kw - 2;
                if (w < 0 || w >= S) continue;
                const float* xp = x2b + i * PLANE + w;
                const float* wp = w_ww + i * (S * 5) + kw;
#pragma unroll
                for (int hh = 0; hh < 4; hh++) {
                    int h = lane + hh * 32;
                    acc = fmaf(xp[h * S], wp[h * 5], acc);
                }
            }
        }
    } else {
#pragma unroll
        for (int i = 0; i < 2; i++) {
#pragma unroll
            for (int kh = 0; kh < 5; kh++) {
                int h = o + kh - 2;
                if (h < 0 || h >= S) continue;
                const float* xp = x2b + i * PLANE + h * S;
                const float* wp = w_hw + i * (5 * S) + kh * S;
#pragma unroll
                for (int wwi = 0; wwi < 4; wwi++) {
                    int w = lane + wwi * 32;
                    acc = fmaf(xp[w], wp[w], acc);
                }
            }
        }
    }

#pragma unroll
    for (int off = 16; off > 0; off >>= 1)
        acc += __shfl_down_sync(0xFFFFFFFFu, acc, off);

    if (lane == 0) {
        if (branch == 0) g_ww_raw[b * S + o] = acc;
        else             g_hw_raw[b * S + o] = acc;
    }
}

// ---------------------------------------------------------------------------
// K3: linear + sigmoid on both [16,128] vectors, then outer product.
// One block per batch element.
//   ww[b,j] = sigmoid(sum_k ww_raw[b,k] * ww_lin_w[j,k] + ww_lin_b[j])
//   out[b,h,w] = hw[b,h] * ww[b,w]
// ---------------------------------------------------------------------------
__global__ void __launch_bounds__(256) k_finish(const float* __restrict__ ww_lw,
                                                const float* __restrict__ ww_lb,
                                                const float* __restrict__ hw_lw,
                                                const float* __restrict__ hw_lb,
                                                float* __restrict__ out) {
    int b = blockIdx.x;
    int t = threadIdx.x;

    __shared__ float s_in[2 * S];
    __shared__ __align__(16) float s_ww[S];
    __shared__ float s_hw[S];

    if (t < S) s_in[t] = g_ww_raw[b * S + t];
    else       s_in[t] = g_hw_raw[b * S + (t - S)];
    __syncthreads();

    if (t < S) {
        float acc = ww_lb[t];
        const float* row = ww_lw + t * S;
#pragma unroll 4
        for (int k = 0; k < S; k++) acc = fmaf(s_in[k], row[k], acc);
        s_ww[t] = 1.f / (1.f + expf(-acc));
    } else {
        int j = t - S;
        float acc = hw_lb[j];
        const float* row = hw_lw + j * S;
#pragma unroll 4
        for (int k = 0; k < S; k++) acc = fmaf(s_in[S + k], row[k], acc);
        s_hw[j] = 1.f / (1.f + expf(-acc));
    }
    __syncthreads();

    float4* o4 = reinterpret_cast<float4*>(out + (size_t)b * PLANE);
    const float4* wv4 = reinterpret_cast<const float4*>(s_ww);
    for (int q = t; q < PLANE4; q += 256) {
        int h  = q >> 5;     // 32 float4 per row
        int w4 = q & 31;
        float hv = s_hw[h];
        float4 wv = wv4[w4];
        o4[q] = make_float4(hv * wv.x, hv * wv.y, hv * wv.z, hv * wv.w);
    }
}

// ---------------------------------------------------------------------------
// Inputs (metadata order):
//  0: x        [16,512,128,128] f32
//  1: w_conv   [2,512,1,1]      f32
//  2: w_ww_conv[1,2,128,5]      f32
//  3: w_hw_conv[1,2,5,128]      f32
//  4: ww_lin_w [128,128]        f32
//  5: ww_lin_b [128]            f32
//  6: hw_lin_w [128,128]        f32
//  7: hw_lin_b [128]            f32
// out: [16,128,128] f32
// ---------------------------------------------------------------------------
extern "C" void kernel_launch(void* const* d_in, const int* in_sizes, int n_in,
                              void* d_out, int out_size) {
    const float* x      = (const float*)d_in[0];
    const float* w_conv = (const float*)d_in[1];
    const float* w_ww   = (const float*)d_in[2];
    const float* w_hw   = (const float*)d_in[3];
    const float* ww_lw  = (const float*)d_in[4];
    const float* ww_lb  = (const float*)d_in[5];
    const float* hw_lw  = (const float*)d_in[6];
    const float* hw_lb  = (const float*)d_in[7];
    float* out = (float*)d_out;

    // K1: 65536 threads, one per float4 pixel group
    k_conv1x1<<<512, 128>>>(x, w_conv);
    // K2: 4096 warps = 131072 threads
    k_stripconv<<<512, 256>>>(w_ww, w_hw);
    // K3: one block per batch element
    k_finish<<<BATCH, 256>>>(ww_lw, ww_lb, hw_lw, hw_lb, out);
}

// round 2
// speedup vs baseline: 1.1897x; 1.1897x over previous
#include <cuda_runtime.h>
#include <math.h>

#define BATCH 16
#define DIM   512
#define S     128
#define PLANE (S*S)            // 16384 floats per channel plane
#define PLANE4 (PLANE/4)       // 4096 float4
#define CSPLIT 4
#define CPER  (DIM/CSPLIT)     // 128 channels per split

// Scratch (allocation-free rule: __device__ globals)
__device__ float g_x2[BATCH * 2 * PLANE];     // [b][o][h][w]  (2 MB)
__device__ float g_ww_raw[BATCH * S];
__device__ float g_hw_raw[BATCH * S];

// ---------------------------------------------------------------------------
// K1: 1x1 conv, 512 -> 2 channels. Split-K over channels (4 splits) within a
// block; explicit 8-deep float4 load batching to force high MLP.
// Block: 256 threads = 64 pixel4-groups x 4 channel-splits. Grid: 1024.
// ---------------------------------------------------------------------------
__global__ void __launch_bounds__(256) k_conv1x1(const float* __restrict__ x,
                                                 const float* __restrict__ wconv) {
    __shared__ float2 s_wc[DIM];                       // 4 KB
    __shared__ float4 red0[CSPLIT][64];                // 4 KB
    __shared__ float4 red1[CSPLIT][64];                // 4 KB

    for (int c = threadIdx.x; c < DIM; c += 256)
        s_wc[c] = make_float2(wconv[c], wconv[DIM + c]);
    __syncthreads();

    int p_in_blk = threadIdx.x & 63;
    int s        = threadIdx.x >> 6;                   // channel split 0..3
    int gp = blockIdx.x * 64 + p_in_blk;               // global pixel4 id
    int b  = gp >> 12;
    int p  = gp & 4095;

    const float4* xb = reinterpret_cast<const float4*>(x)
                     + (size_t)b * DIM * PLANE4 + (size_t)s * CPER * PLANE4 + p;

    float4 a0 = make_float4(0.f, 0.f, 0.f, 0.f);
    float4 a1 = make_float4(0.f, 0.f, 0.f, 0.f);

    for (int c0 = 0; c0 < CPER; c0 += 8) {
        float4 v[8];
#pragma unroll
        for (int j = 0; j < 8; j++)
            v[j] = xb[(size_t)(c0 + j) * PLANE4];
#pragma unroll
        for (int j = 0; j < 8; j++) {
            float2 wc = s_wc[s * CPER + c0 + j];
            a0.x = fmaf(v[j].x, wc.x, a0.x); a0.y = fmaf(v[j].y, wc.x, a0.y);
            a0.z = fmaf(v[j].z, wc.x, a0.z); a0.w = fmaf(v[j].w, wc.x, a0.w);
            a1.x = fmaf(v[j].x, wc.y, a1.x); a1.y = fmaf(v[j].y, wc.y, a1.y);
            a1.z = fmaf(v[j].z, wc.y, a1.z); a1.w = fmaf(v[j].w, wc.y, a1.w);
        }
    }

    red0[s][p_in_blk] = a0;
    red1[s][p_in_blk] = a1;
    __syncthreads();

    if (threadIdx.x < 128) {
        int ch = threadIdx.x >> 6;
        int pp = threadIdx.x & 63;
        float4 r;
        if (ch == 0) {
            float4 r0 = red0[0][pp], r1 = red0[1][pp], r2 = red0[2][pp], r3 = red0[3][pp];
            r = make_float4(r0.x + r1.x + r2.x + r3.x, r0.y + r1.y + r2.y + r3.y,
                            r0.z + r1.z + r2.z + r3.z, r0.w + r1.w + r2.w + r3.w);
        } else {
            float4 r0 = red1[0][pp], r1 = red1[1][pp], r2 = red1[2][pp], r3 = red1[3][pp];
            r = make_float4(r0.x + r1.x + r2.x + r3.x, r0.y + r1.y + r2.y + r3.y,
                            r0.z + r1.z + r2.z + r3.z, r0.w + r1.w + r2.w + r3.w);
        }
        float4* o = reinterpret_cast<float4*>(g_x2)
                  + (size_t)b * 2 * PLANE4 + (size_t)ch * PLANE4
                  + (blockIdx.x & 63) * 64 + pp;
        *o = r;
    }
}

// ---------------------------------------------------------------------------
// K2: strip-conv reductions with fully coalesced loads.
// Grid: 32 blocks = (b, branch). 256 threads.
//
// ww branch: T[kw][w'] = sum_{i,h} x2[b,i,h,w'] * w_ww[i,h,kw]
//            ww[b,w]  = sum_kw T[kw][w+kw-2]        (column loads coalesced
//            across threads; each load feeds 5 FMAs)
// hw branch: R[kh][h'] = sum_{i,w} x2[b,i,h',w] * w_hw[i,kh,w]
//            hw[b,h]  = sum_kh R[kh][h+kh-2]        (warp-per-row, lanes over
//            w -> coalesced; shfl reduce)
// ---------------------------------------------------------------------------
__global__ void __launch_bounds__(256) k_stripconv(const float* __restrict__ w_ww,
                                                   const float* __restrict__ w_hw) {
    int b      = blockIdx.x >> 1;
    int branch = blockIdx.x & 1;
    int tid    = threadIdx.x;
    const float* x2b = g_x2 + (size_t)b * 2 * PLANE;

    __shared__ float s_w[2 * S * 5];                   // 5 KB weights
    __shared__ float s_T[5][S + 4];                    // partial T/R, padded halo

    if (branch == 0) {
        // --- ww branch ---
        for (int k = tid; k < 2 * S * 5; k += 256) s_w[k] = w_ww[k];  // [i][h][kw]
        __syncthreads();

        int i = tid >> 7;          // channel 0/1
        int w = tid & 127;         // column
        const float* xp = x2b + i * PLANE + w;
        float A[5] = {0.f, 0.f, 0.f, 0.f, 0.f};
#pragma unroll 8
        for (int h = 0; h < S; h++) {
            float v = xp[h * S];                       // coalesced across w
            const float* wt = &s_w[i * S * 5 + h * 5];
#pragma unroll
            for (int kw = 0; kw < 5; kw++) A[kw] = fmaf(v, wt[kw], A[kw]);
        }
        // combine the two channels: i=0 writes, i=1 adds via smem
        if (i == 0) {
#pragma unroll
            for (int kw = 0; kw < 5; kw++) s_T[kw][w + 2] = A[kw];
        }
        __syncthreads();
        if (i == 1) {
#pragma unroll
            for (int kw = 0; kw < 5; kw++) s_T[kw][w + 2] += A[kw];
        }
        __syncthreads();
        if (tid < S) {
            int w0 = tid;
            float acc = 0.f;
#pragma unroll
            for (int kw = 0; kw < 5; kw++) {
                int wp = w0 + kw - 2;
                if (wp >= 0 && wp < S) acc += s_T[kw][wp + 2];
            }
            g_ww_raw[b * S + w0] = acc;
        }
    } else {
        // --- hw branch ---
        for (int k = tid; k < 2 * 5 * S; k += 256) s_w[k] = w_hw[k];  // [i][kh][w]
        __syncthreads();

        int warp = tid >> 5, lane = tid & 31;
        for (int h2 = warp; h2 < S; h2 += 8) {
            float A[5] = {0.f, 0.f, 0.f, 0.f, 0.f};
#pragma unroll
            for (int i = 0; i < 2; i++) {
                const float* row = x2b + i * PLANE + h2 * S;
                const float* wt  = &s_w[i * 5 * S];
#pragma unroll
                for (int j = 0; j < 4; j++) {
                    int w = lane + 32 * j;
                    float v = row[w];                  // coalesced over lanes
#pragma unroll
                    for (int kh = 0; kh < 5; kh++)
                        A[kh] = fmaf(v, wt[kh * S + w], A[kh]);
                }
            }
#pragma unroll
            for (int kh = 0; kh < 5; kh++) {
#pragma unroll
                for (int off = 16; off > 0; off >>= 1)
                    A[kh] += __shfl_down_sync(0xFFFFFFFFu, A[kh], off);
            }
            if (lane == 0) {
#pragma unroll
                for (int kh = 0; kh < 5; kh++) s_T[kh][h2 + 2] = A[kh];
            }
        }
        __syncthreads();
        if (tid < S) {
            int h0 = tid;
            float acc = 0.f;
#pragma unroll
            for (int kh = 0; kh < 5; kh++) {
                int hp = h0 + kh - 2;
                if (hp >= 0 && hp < S) acc += s_T[kh][hp + 2];
            }
            g_hw_raw[b * S + h0] = acc;
        }
    }
}

// ---------------------------------------------------------------------------
// K3: linear + sigmoid on both [16,128] vectors, then outer product.
// ---------------------------------------------------------------------------
__global__ void __launch_bounds__(256) k_finish(const float* __restrict__ ww_lw,
                                                const float* __restrict__ ww_lb,
                                                const float* __restrict__ hw_lw,
                                                const float* __restrict__ hw_lb,
                                                float* __restrict__ out) {
    int b = blockIdx.x;
    int t = threadIdx.x;

    __shared__ float s_in[2 * S];
    __shared__ __align__(16) float s_ww[S];
    __shared__ float s_hw[S];

    if (t < S) s_in[t] = g_ww_raw[b * S + t];
    else       s_in[t] = g_hw_raw[b * S + (t - S)];
    __syncthreads();

    if (t < S) {
        float acc = ww_lb[t];
        const float* row = ww_lw + t * S;
#pragma unroll 4
        for (int k = 0; k < S; k++) acc = fmaf(s_in[k], row[k], acc);
        s_ww[t] = 1.f / (1.f + expf(-acc));
    } else {
        int j = t - S;
        float acc = hw_lb[j];
        const float* row = hw_lw + j * S;
#pragma unroll 4
        for (int k = 0; k < S; k++) acc = fmaf(s_in[S + k], row[k], acc);
        s_hw[j] = 1.f / (1.f + expf(-acc));
    }
    __syncthreads();

    float4* o4 = reinterpret_cast<float4*>(out + (size_t)b * PLANE);
    const float4* wv4 = reinterpret_cast<const float4*>(s_ww);
    for (int q = t; q < PLANE4; q += 256) {
        int h  = q >> 5;
        int w4 = q & 31;
        float hv = s_hw[h];
        float4 wv = wv4[w4];
        o4[q] = make_float4(hv * wv.x, hv * wv.y, hv * wv.z, hv * wv.w);
    }
}

// ---------------------------------------------------------------------------
extern "C" void kernel_launch(void* const* d_in, const int* in_sizes, int n_in,
                              void* d_out, int out_size) {
    const float* x      = (const float*)d_in[0];
    const float* w_conv = (const float*)d_in[1];
    const float* w_ww   = (const float*)d_in[2];
    const float* w_hw   = (const float*)d_in[3];
    const float* ww_lw  = (const float*)d_in[4];
    const float* ww_lb  = (const float*)d_in[5];
    const float* hw_lw  = (const float*)d_in[6];
    const float* hw_lb  = (const float*)d_in[7];
    float* out = (float*)d_out;

    k_conv1x1<<<1024, 256>>>(x, w_conv);
    k_stripconv<<<32, 256>>>(w_ww, w_hw);
    k_finish<<<BATCH, 256>>>(ww_lw, ww_lb, hw_lw, hw_lb, out);
}

// round 4
// speedup vs baseline: 1.2358x; 1.0387x over previous
#include <cuda_runtime.h>
#include <math.h>

#define BATCH 16
#define DIM   512
#define S     128
#define PLANE (S*S)
#define PLANE4 (PLANE/4)
#define CSPLIT 4
#define CPER  (DIM/CSPLIT)     // 128 channels per split

// Accumulator for fused strip-conv partials:
// g_TR[b][0..4][w]   = T[kw][w']  (ww branch, pre-halo)
// g_TR[b][5..9][h]   = R[kh][h']  (hw branch, pre-halo)
__device__ float g_TR[BATCH * 10 * S];     // 80 KB, zeroed by memset each call

// ---------------------------------------------------------------------------
// K1: 1x1 conv 512->2 fused with strip-conv partial reductions.
// Block = 128 threads = 32 pixel4 (one image row) x 4 channel-splits.
// Grid = 2048 (16 b x 128 rows). No x2 ever written to DRAM.
// ---------------------------------------------------------------------------
__global__ void __launch_bounds__(128) k_conv_fused(const float* __restrict__ x,
                                                    const float* __restrict__ wconv,
                                                    const float* __restrict__ w_ww,
                                                    const float* __restrict__ w_hw) {
    __shared__ float2 s_wc[DIM];          // 4 KB
    __shared__ float4 red0[CSPLIT][32];   // 2 KB
    __shared__ float4 red1[CSPLIT][32];   // 2 KB
    __shared__ float  s_T[5][S];          // 2.5 KB

    int tid = threadIdx.x;
    for (int c = tid; c < DIM; c += 128)
        s_wc[c] = make_float2(wconv[c], wconv[DIM + c]);
    for (int k = tid; k < 5 * S; k += 128)
        (&s_T[0][0])[k] = 0.f;
    __syncthreads();

    int s = tid >> 5;                  // channel split 0..3
    int p = tid & 31;                  // pixel4 within row
    int b  = blockIdx.x >> 7;          // 128 row-blocks per batch image
    int rb = blockIdx.x & 127;         // row index

    const float4* xb = reinterpret_cast<const float4*>(x)
                     + (size_t)b * DIM * PLANE4
                     + (size_t)s * CPER * PLANE4
                     + (size_t)rb * 32 + p;

    float4 a0 = make_float4(0.f, 0.f, 0.f, 0.f);
    float4 a1 = make_float4(0.f, 0.f, 0.f, 0.f);

    for (int c0 = 0; c0 < CPER; c0 += 8) {
        float4 v[8];
#pragma unroll
        for (int j = 0; j < 8; j++)
            v[j] = xb[(size_t)(c0 + j) * PLANE4];
#pragma unroll
        for (int j = 0; j < 8; j++) {
            float2 wc = s_wc[s * CPER + c0 + j];
            a0.x = fmaf(v[j].x, wc.x, a0.x); a0.y = fmaf(v[j].y, wc.x, a0.y);
            a0.z = fmaf(v[j].z, wc.x, a0.z); a0.w = fmaf(v[j].w, wc.x, a0.w);
            a1.x = fmaf(v[j].x, wc.y, a1.x); a1.y = fmaf(v[j].y, wc.y, a1.y);
            a1.z = fmaf(v[j].z, wc.y, a1.z); a1.w = fmaf(v[j].w, wc.y, a1.w);
        }
    }

    red0[s][p] = a0;
    red1[s][p] = a1;
    __syncthreads();

    // Threads 0..63: ch = tid>>5, pixel4 = tid&31. Combine splits -> final x2
    // value for (b, ch, row rb, w = 4*pp .. 4*pp+3), then emit strip-conv
    // partials. Warp 0 = ch0 over full row, warp 1 = ch1 (shfl-reducible).
    if (tid < 64) {
        int ch = tid >> 5;
        int pp = tid & 31;
        float4 r;
        {
            float4 q0, q1, q2, q3;
            if (ch == 0) { q0 = red0[0][pp]; q1 = red0[1][pp]; q2 = red0[2][pp]; q3 = red0[3][pp]; }
            else         { q0 = red1[0][pp]; q1 = red1[1][pp]; q2 = red1[2][pp]; q3 = red1[3][pp]; }
            r = make_float4(q0.x + q1.x + q2.x + q3.x, q0.y + q1.y + q2.y + q3.y,
                            q0.z + q1.z + q2.z + q3.z, q0.w + q1.w + q2.w + q3.w);
        }
        int w0 = pp * 4;

        // T[kw][w'] += x2[ch, rb, w'] * w_ww[ch, rb, kw]   (w_ww: [2,128,5])
#pragma unroll
        for (int kw = 0; kw < 5; kw++) {
            float wt = __ldg(&w_ww[(ch * S + rb) * 5 + kw]);
            atomicAdd(&s_T[kw][w0 + 0], r.x * wt);
            atomicAdd(&s_T[kw][w0 + 1], r.y * wt);
            atomicAdd(&s_T[kw][w0 + 2], r.z * wt);
            atomicAdd(&s_T[kw][w0 + 3], r.w * wt);
        }

        // R[kh][rb] += sum_w x2[ch, rb, w] * w_hw[ch, kh, w]   (w_hw: [2,5,128])
#pragma unroll
        for (int kh = 0; kh < 5; kh++) {
            const float* whp = w_hw + (ch * 5 + kh) * S + w0;
            float pr = r.x * __ldg(whp) + r.y * __ldg(whp + 1)
                     + r.z * __ldg(whp + 2) + r.w * __ldg(whp + 3);
#pragma unroll
            for (int off = 16; off > 0; off >>= 1)
                pr += __shfl_down_sync(0xFFFFFFFFu, pr, off);
            if (pp == 0)
                atomicAdd(&g_TR[b * (10 * S) + (5 + kh) * S + rb], pr);
        }
    }
    __syncthreads();

    // Flush block-local T to global accumulator
    for (int k = tid; k < 5 * S; k += 128)
        atomicAdd(&g_TR[b * (10 * S) + k], (&s_T[0][0])[k]);
}

// ---------------------------------------------------------------------------
// K_final: halo-combine T/R, linear + sigmoid, outer product. One block per b.
// ---------------------------------------------------------------------------
__global__ void __launch_bounds__(256) k_final(const float* __restrict__ ww_lw,
                                               const float* __restrict__ ww_lb,
                                               const float* __restrict__ hw_lw,
                                               const float* __restrict__ hw_lb,
                                               float* __restrict__ out) {
    int b = blockIdx.x;
    int t = threadIdx.x;

    __shared__ float sTR[10 * S];          // 5 KB
    __shared__ float s_in[2 * S];          // ww_in [0:128], hw_in [128:256]
    __shared__ __align__(16) float s_ww[S];
    __shared__ float s_hw[S];

    for (int k = t; k < 10 * S; k += 256)
        sTR[k] = g_TR[b * (10 * S) + k];
    __syncthreads();

    if (t < S) {
        float acc = 0.f;
#pragma unroll
        for (int kw = 0; kw < 5; kw++) {
            int wp = t + kw - 2;
            if (wp >= 0 && wp < S) acc += sTR[kw * S + wp];
        }
        s_in[t] = acc;
    } else {
        int h = t - S;
        float acc = 0.f;
#pragma unroll
        for (int kh = 0; kh < 5; kh++) {
            int hp = h + kh - 2;
            if (hp >= 0 && hp < S) acc += sTR[(5 + kh) * S + hp];
        }
        s_in[t] = acc;
    }
    __syncthreads();

    if (t < S) {
        float acc = ww_lb[t];
        const float* row = ww_lw + t * S;
#pragma unroll 4
        for (int k = 0; k < S; k++) acc = fmaf(s_in[k], row[k], acc);
        s_ww[t] = 1.f / (1.f + expf(-acc));
    } else {
        int j = t - S;
        float acc = hw_lb[j];
        const float* row = hw_lw + j * S;
#pragma unroll 4
        for (int k = 0; k < S; k++) acc = fmaf(s_in[S + k], row[k], acc);
        s_hw[j] = 1.f / (1.f + expf(-acc));
    }
    __syncthreads();

    float4* o4 = reinterpret_cast<float4*>(out + (size_t)b * PLANE);
    const float4* wv4 = reinterpret_cast<const float4*>(s_ww);
    for (int q = t; q < PLANE4; q += 256) {
        int h  = q >> 5;
        int w4 = q & 31;
        float hv = s_hw[h];
        float4 wv = wv4[w4];
        o4[q] = make_float4(hv * wv.x, hv * wv.y, hv * wv.z, hv * wv.w);
    }
}

// ---------------------------------------------------------------------------
extern "C" void kernel_launch(void* const* d_in, const int* in_sizes, int n_in,
                              void* d_out, int out_size) {
    const float* x      = (const float*)d_in[0];
    const float* w_conv = (const float*)d_in[1];
    const float* w_ww   = (const float*)d_in[2];
    const float* w_hw   = (const float*)d_in[3];
    const float* ww_lw  = (const float*)d_in[4];
    const float* ww_lb  = (const float*)d_in[5];
    const float* hw_lw  = (const float*)d_in[6];
    const float* hw_lb  = (const float*)d_in[7];
    float* out = (float*)d_out;

    void* tr_addr = nullptr;
    cudaGetSymbolAddress(&tr_addr, g_TR);
    cudaMemsetAsync(tr_addr, 0, sizeof(float) * BATCH * 10 * S);

    k_conv_fused<<<2048, 128>>>(x, w_conv, w_ww, w_hw);
    k_final<<<BATCH, 256>>>(ww_lw, ww_lb, hw_lw, hw_lb, out);
}

// round 5
// speedup vs baseline: 1.5008x; 1.2144x over previous
#include <cuda_runtime.h>
#include <math.h>

#define BATCH 16
#define DIM   512
#define S     128
#define PLANE (S*S)
#define PLANE4 (PLANE/4)
#define CSPLIT 4
#define CPER  (DIM/CSPLIT)     // 128 channels per split

// Accumulator for fused strip-conv partials:
// g_TR[b][0..4][w]   = T[kw][w']  (ww branch, pre-halo)
// g_TR[b][5..9][h]   = R[kh][h']  (hw branch, pre-halo)
__device__ float g_TR[BATCH * 10 * S];     // 80 KB, zeroed by memset each call
__device__ float g_vec[BATCH * 2 * S];     // sigmoid outputs: [b][0]=ww, [b][1]=hw

// ---------------------------------------------------------------------------
// K1: 1x1 conv 512->2 fused with strip-conv partial reductions.
// Block = 128 threads = 32 pixel4 (one image row) x 4 channel-splits.
// Grid = 2048 (16 b x 128 rows). No x2 ever written to DRAM.
// ---------------------------------------------------------------------------
__global__ void __launch_bounds__(128) k_conv_fused(const float* __restrict__ x,
                                                    const float* __restrict__ wconv,
                                                    const float* __restrict__ w_ww,
                                                    const float* __restrict__ w_hw) {
    __shared__ float2 s_wc[DIM];          // 4 KB
    __shared__ float4 red0[CSPLIT][32];   // 2 KB
    __shared__ float4 red1[CSPLIT][32];   // 2 KB
    __shared__ float  s_T[5][S];          // 2.5 KB

    int tid = threadIdx.x;
    for (int c = tid; c < DIM; c += 128)
        s_wc[c] = make_float2(wconv[c], wconv[DIM + c]);
    for (int k = tid; k < 5 * S; k += 128)
        (&s_T[0][0])[k] = 0.f;
    __syncthreads();

    int s = tid >> 5;                  // channel split 0..3
    int p = tid & 31;                  // pixel4 within row
    int b  = blockIdx.x >> 7;          // 128 row-blocks per batch image
    int rb = blockIdx.x & 127;         // row index

    const float4* xb = reinterpret_cast<const float4*>(x)
                     + (size_t)b * DIM * PLANE4
                     + (size_t)s * CPER * PLANE4
                     + (size_t)rb * 32 + p;

    float4 a0 = make_float4(0.f, 0.f, 0.f, 0.f);
    float4 a1 = make_float4(0.f, 0.f, 0.f, 0.f);

    for (int c0 = 0; c0 < CPER; c0 += 8) {
        float4 v[8];
#pragma unroll
        for (int j = 0; j < 8; j++)
            v[j] = xb[(size_t)(c0 + j) * PLANE4];
#pragma unroll
        for (int j = 0; j < 8; j++) {
            float2 wc = s_wc[s * CPER + c0 + j];
            a0.x = fmaf(v[j].x, wc.x, a0.x); a0.y = fmaf(v[j].y, wc.x, a0.y);
            a0.z = fmaf(v[j].z, wc.x, a0.z); a0.w = fmaf(v[j].w, wc.x, a0.w);
            a1.x = fmaf(v[j].x, wc.y, a1.x); a1.y = fmaf(v[j].y, wc.y, a1.y);
            a1.z = fmaf(v[j].z, wc.y, a1.z); a1.w = fmaf(v[j].w, wc.y, a1.w);
        }
    }

    red0[s][p] = a0;
    red1[s][p] = a1;
    __syncthreads();

    // Threads 0..63: combine splits -> final x2 row values, emit partials.
    if (tid < 64) {
        int ch = tid >> 5;
        int pp = tid & 31;
        float4 r;
        {
            float4 q0, q1, q2, q3;
            if (ch == 0) { q0 = red0[0][pp]; q1 = red0[1][pp]; q2 = red0[2][pp]; q3 = red0[3][pp]; }
            else         { q0 = red1[0][pp]; q1 = red1[1][pp]; q2 = red1[2][pp]; q3 = red1[3][pp]; }
            r = make_float4(q0.x + q1.x + q2.x + q3.x, q0.y + q1.y + q2.y + q3.y,
                            q0.z + q1.z + q2.z + q3.z, q0.w + q1.w + q2.w + q3.w);
        }
        int w0 = pp * 4;

        // T[kw][w'] += x2[ch, rb, w'] * w_ww[ch, rb, kw]   (w_ww: [2,128,5])
#pragma unroll
        for (int kw = 0; kw < 5; kw++) {
            float wt = __ldg(&w_ww[(ch * S + rb) * 5 + kw]);
            atomicAdd(&s_T[kw][w0 + 0], r.x * wt);
            atomicAdd(&s_T[kw][w0 + 1], r.y * wt);
            atomicAdd(&s_T[kw][w0 + 2], r.z * wt);
            atomicAdd(&s_T[kw][w0 + 3], r.w * wt);
        }

        // R[kh][rb] += sum_w x2[ch, rb, w] * w_hw[ch, kh, w]   (w_hw: [2,5,128])
#pragma unroll
        for (int kh = 0; kh < 5; kh++) {
            const float* whp = w_hw + (ch * 5 + kh) * S + w0;
            float pr = r.x * __ldg(whp) + r.y * __ldg(whp + 1)
                     + r.z * __ldg(whp + 2) + r.w * __ldg(whp + 3);
#pragma unroll
            for (int off = 16; off > 0; off >>= 1)
                pr += __shfl_down_sync(0xFFFFFFFFu, pr, off);
            if (pp == 0)
                atomicAdd(&g_TR[b * (10 * S) + (5 + kh) * S + rb], pr);
        }
    }
    __syncthreads();

    // Flush block-local T to global accumulator
    for (int k = tid; k < 5 * S; k += 128)
        atomicAdd(&g_TR[b * (10 * S) + k], (&s_T[0][0])[k]);
}

// ---------------------------------------------------------------------------
// K2: halo-combine + linear + sigmoid. Grid = 32 (b x branch), 256 threads.
// Warp-per-output GEMV: lanes stride over k -> coalesced weight loads.
// ---------------------------------------------------------------------------
__global__ void __launch_bounds__(256) k_vec(const float* __restrict__ ww_lw,
                                             const float* __restrict__ ww_lb,
                                             const float* __restrict__ hw_lw,
                                             const float* __restrict__ hw_lb) {
    int b      = blockIdx.x >> 1;
    int branch = blockIdx.x & 1;       // 0 = ww, 1 = hw
    int tid    = threadIdx.x;
    int warp   = tid >> 5, lane = tid & 31;

    const float* lw = branch ? hw_lw : ww_lw;
    const float* lb = branch ? hw_lb : ww_lb;
    const float* TR = g_TR + b * (10 * S) + branch * (5 * S);

    __shared__ float s_in[S];

    if (tid < S) {
        float acc = 0.f;
#pragma unroll
        for (int k5 = 0; k5 < 5; k5++) {
            int ip = tid + k5 - 2;
            if (ip >= 0 && ip < S) acc += TR[k5 * S + ip];
        }
        s_in[tid] = acc;
    }
    __syncthreads();

    // 8 warps x 16 outputs each
    for (int j = warp; j < S; j += 8) {
        const float* row = lw + j * S;
        float acc = 0.f;
#pragma unroll
        for (int kk = 0; kk < 4; kk++) {
            int k = lane + kk * 32;
            acc = fmaf(s_in[k], __ldg(&row[k]), acc);   // coalesced over lanes
        }
#pragma unroll
        for (int off = 16; off > 0; off >>= 1)
            acc += __shfl_down_sync(0xFFFFFFFFu, acc, off);
        if (lane == 0) {
            acc += __ldg(&lb[j]);
            g_vec[(b * 2 + branch) * S + j] = 1.f / (1.f + expf(-acc));
        }
    }
}

// ---------------------------------------------------------------------------
// K3: outer product, full-chip. 256 blocks x 256 threads, one float4/thread.
// out[b,h,w] = hw[b,h] * ww[b,w]
// ---------------------------------------------------------------------------
__global__ void __launch_bounds__(256) k_outer(float* __restrict__ out) {
    int gid = blockIdx.x * 256 + threadIdx.x;   // 0 .. 65535
    int b   = gid >> 12;
    int rem = gid & 4095;
    int h   = rem >> 5;
    int w4  = rem & 31;

    float hv = __ldg(&g_vec[(b * 2 + 1) * S + h]);
    float4 wv = __ldg(reinterpret_cast<const float4*>(&g_vec[(b * 2 + 0) * S]) + w4);

    reinterpret_cast<float4*>(out)[gid] =
        make_float4(hv * wv.x, hv * wv.y, hv * wv.z, hv * wv.w);
}

// ---------------------------------------------------------------------------
extern "C" void kernel_launch(void* const* d_in, const int* in_sizes, int n_in,
                              void* d_out, int out_size) {
    const float* x      = (const float*)d_in[0];
    const float* w_conv = (const float*)d_in[1];
    const float* w_ww   = (const float*)d_in[2];
    const float* w_hw   = (const float*)d_in[3];
    const float* ww_lw  = (const float*)d_in[4];
    const float* ww_lb  = (const float*)d_in[5];
    const float* hw_lw  = (const float*)d_in[6];
    const float* hw_lb  = (const float*)d_in[7];
    float* out = (float*)d_out;

    void* tr_addr = nullptr;
    cudaGetSymbolAddress(&tr_addr, g_TR);
    cudaMemsetAsync(tr_addr, 0, sizeof(float) * BATCH * 10 * S);

    k_conv_fused<<<2048, 128>>>(x, w_conv, w_ww, w_hw);
    k_vec<<<32, 256>>>(ww_lw, ww_lb, hw_lw, hw_lb);
    k_outer<<<256, 256>>>(out);
}